// round 12
// baseline (speedup 1.0000x reference)
#include <cuda_runtime.h>
#include <cuda_fp16.h>
#include <math.h>
#include <stdint.h>

// ---------------------------------------------------------------------------
// Problem constants
// ---------------------------------------------------------------------------
#define BATCH   8
#define SEQ     2048
#define DIM     512
#define NTOK    (BATCH * SEQ)          // 16384

// GEMM tiling (mma.sync m16n8k16 fp16)
#define BM 256
#define BN 128
#define BK 64                          // fp16 K per stage
#define NTHREADS 512                   // 16 warps: 4 (m) x 4 (n), 64x32 warp tiles
#define STAGES 3

// smem pitch in fp16: 64 k + 8 pad = 72 (144B rows; ldmatrix conflict-free)
#define PA 72
#define SBUFA (256 * PA)               // fp16 elements (A: 256 rows)
#define SBUFB (128 * PA)               // fp16 elements (B: 128 rows)
#define STAGE_H (SBUFA + SBUFB)
#define SMEM_BYTES_G (STAGES * STAGE_H * 2)   // 165,888 B -> 1 CTA/SM

// Epilogue tags
#define EPI_GATE     0
#define EPI_SCALE    1
#define EPI_ADD      2
#define EPI_GELU     3
#define EPI_BIAS_RES 4

// ---------------------------------------------------------------------------
// Scratch (device globals: allocation-free rule)
// ---------------------------------------------------------------------------
__device__ float  g_fused  [(size_t)NTOK * DIM];
__device__ float  g_q      [(size_t)NTOK * DIM];
__device__ float  g_y      [(size_t)NTOK * DIM];
__device__ __half g_fusedh [(size_t)NTOK * DIM];
__device__ __half g_attnh  [(size_t)BATCH * SEQ * SEQ];  // logits then weights
__device__ __half g_qh     [(size_t)NTOK * DIM];
__device__ __half g_hh     [(size_t)NTOK * 2 * DIM];
__device__ __half g_noiseh [(size_t)NTOK * DIM];
__device__ __half g_condh  [(size_t)NTOK * DIM];
__device__ __half g_xh     [(size_t)NTOK * DIM];         // X fp16 [S,D]
__device__ __half g_xth    [(size_t)BATCH * DIM * SEQ];  // X^T fp16 [D,S]
__device__ __half g_wgth   [(size_t)DIM * 2 * DIM];
__device__ __half g_w1th   [(size_t)2 * DIM * DIM];
__device__ __half g_w2th   [(size_t)DIM * 2 * DIM];

// ---------------------------------------------------------------------------
// PTX helpers
// ---------------------------------------------------------------------------
__device__ __forceinline__ uint32_t smem_u32(const void* p) {
    uint32_t a;
    asm("{ .reg .u64 t; cvta.to.shared.u64 t, %1; cvt.u32.u64 %0, t; }" : "=r"(a) : "l"(p));
    return a;
}
__device__ __forceinline__ void cp16(uint32_t saddr, const void* gaddr) {
    asm volatile("cp.async.cg.shared.global [%0], [%1], 16;" :: "r"(saddr), "l"(gaddr));
}
__device__ __forceinline__ void cp_commit() {
    asm volatile("cp.async.commit_group;" ::: "memory");
}
template<int N>
__device__ __forceinline__ void cp_wait() {
    asm volatile("cp.async.wait_group %0;" :: "n"(N) : "memory");
}
__device__ __forceinline__ void mma_f16(float* c, uint32_t a0, uint32_t a1,
                                        uint32_t a2, uint32_t a3,
                                        uint32_t b0, uint32_t b1) {
    asm volatile("mma.sync.aligned.m16n8k16.row.col.f32.f16.f16.f32 "
                 "{%0,%1,%2,%3}, {%4,%5,%6,%7}, {%8,%9}, {%0,%1,%2,%3};"
                 : "+f"(c[0]), "+f"(c[1]), "+f"(c[2]), "+f"(c[3])
                 : "r"(a0), "r"(a1), "r"(a2), "r"(a3), "r"(b0), "r"(b1));
}
__device__ __forceinline__ void ldsm4(uint32_t& r0, uint32_t& r1, uint32_t& r2,
                                      uint32_t& r3, uint32_t addr) {
    asm volatile("ldmatrix.sync.aligned.m8n8.x4.shared.b16 {%0,%1,%2,%3}, [%4];"
                 : "=r"(r0), "=r"(r1), "=r"(r2), "=r"(r3) : "r"(addr));
}

// ---------------------------------------------------------------------------
// fp16 tensor-core GEMM: C[M,N] = A[M,K] * B^T, A [M,K], B [N,K] (K-contig).
// 256x128x64 CTA tile, 16 warps (4x4), 64x32 warp tiles, ldmatrix fragments,
// 3-stage cp.async ring, 1 barrier per K=64 iter.  fp32 accumulate.
// SPLITA: A cols [0,512) from A, [512,1024) from A2 (virtual concat).
// Output: EPI_GATE -> C + Ch; EPI_SCALE, EPI_GELU -> Ch only; else -> C.
// ---------------------------------------------------------------------------
template<int EPI, bool SPLITA>
__global__ void __launch_bounds__(NTHREADS, 1)
gemm_mma(const __half* __restrict__ A, const __half* __restrict__ A2,
         const __half* __restrict__ B,
         float* __restrict__ C, __half* __restrict__ Ch,
         int K, int lda, int ldb, int ldc,
         size_t strA, size_t strB, size_t strC,
         const float* __restrict__ bias,
         const float* __restrict__ res0,
         const float* __restrict__ res1,
         float scale)
{
    extern __shared__ __half hsm[];

    const int z = blockIdx.z;
    A += (size_t)z * strA;
    B += (size_t)z * strB;
    if (C)  C  += (size_t)z * strC;
    if (Ch) Ch += (size_t)z * strC;
    if (res0) res0 += (size_t)z * strC;
    if (res1) res1 += (size_t)z * strC;

    const int bm   = blockIdx.y * BM;
    const int bn   = blockIdx.x * BN;
    const int tid  = threadIdx.x;
    const int wid  = tid >> 5;
    const int lane = tid & 31;
    const int warp_m = wid & 3;        // 0..3 -> 64-row groups (256 rows)
    const int warp_n = wid >> 2;       // 0..3 -> 32-col groups (128 cols)
    const int g  = lane >> 2;          // 0..7
    const int tg = lane & 3;           // 0..3
    const int quad  = lane >> 3;       // 0..3
    const int rowin = lane & 7;        // 0..7

    const int a_row = (quad & 1) * 8 + rowin;
    const int a_col = (quad >> 1) * 8;
    const int b_row = (quad >> 1) * 8 + rowin;
    const int b_col = (quad & 1) * 8;

    const uint32_t smB = smem_u32(hsm);

    float acc[4][4][4];
    #pragma unroll
    for (int i = 0; i < 4; i++)
        #pragma unroll
        for (int j = 0; j < 4; j++)
            #pragma unroll
            for (int e = 0; e < 4; e++) acc[i][j][e] = 0.f;

    const int nit = K / BK;

    // ---- prefetch one K=64 tile (A 256x64, B 128x64 fp16) ----
    auto prefetch = [&](int it) {
        const int kk = it * BK;
        const int st = it % STAGES;
        const uint32_t sa = smB + (uint32_t)(st * STAGE_H) * 2u;
        const uint32_t sb = sa + (uint32_t)SBUFA * 2u;
        // A: 256 rows x 8 chunks (8 fp16) = 2048 chunks -> 4 per thread
        #pragma unroll
        for (int t = 0; t < 4; t++) {
            int id = tid + t * NTHREADS;       // 0..2047
            int r  = id >> 3;                  // 0..255
            int c8 = id & 7;
            int col = kk + c8 * 8;
            const __half* src;
            if (SPLITA) {
                src = (col < DIM) ? (A  + (size_t)(bm + r) * DIM + col)
                                  : (A2 + (size_t)(bm + r) * DIM + (col - DIM));
            } else {
                src = A + (size_t)(bm + r) * lda + col;
            }
            cp16(sa + (uint32_t)(r * PA + c8 * 8) * 2u, src);
        }
        // B: 128 rows x 8 chunks = 1024 chunks -> 2 per thread
        #pragma unroll
        for (int t = 0; t < 2; t++) {
            int id = tid + t * NTHREADS;       // 0..1023
            int r  = id >> 3;                  // 0..127
            int c8 = id & 7;
            cp16(sb + (uint32_t)(r * PA + c8 * 8) * 2u,
                 B + (size_t)(bn + r) * ldb + kk + c8 * 8);
        }
        cp_commit();
    };

    prefetch(0);
    prefetch(1);

    #pragma unroll 1
    for (int it = 0; it < nit; it++) {
        cp_wait<1>();
        __syncthreads();
        if (it + 2 < nit) prefetch(it + 2);

        const int st = it % STAGES;
        const uint32_t sa = smB + (uint32_t)(st * STAGE_H) * 2u;
        const uint32_t sb = sa + (uint32_t)SBUFA * 2u;

        #pragma unroll
        for (int ks = 0; ks < 4; ks++) {       // 4 x k16 per BK=64
            const int kc = ks * 16;
            uint32_t af[4][4];
            #pragma unroll
            for (int mt = 0; mt < 4; mt++) {
                int m = warp_m * 64 + mt * 16;
                uint32_t addr = sa + (uint32_t)((m + a_row) * PA + kc + a_col) * 2u;
                ldsm4(af[mt][0], af[mt][1], af[mt][2], af[mt][3], addr);
            }
            uint32_t bf[4][2];
            #pragma unroll
            for (int np = 0; np < 2; np++) {
                int n = warp_n * 32 + np * 16;
                uint32_t addr = sb + (uint32_t)((n + b_row) * PA + kc + b_col) * 2u;
                ldsm4(bf[np*2][0], bf[np*2][1], bf[np*2+1][0], bf[np*2+1][1], addr);
            }
            #pragma unroll
            for (int mt = 0; mt < 4; mt++)
                #pragma unroll
                for (int nt = 0; nt < 4; nt++)
                    mma_f16(acc[mt][nt], af[mt][0], af[mt][1], af[mt][2], af[mt][3],
                            bf[nt][0], bf[nt][1]);
        }
    }

    // ---- epilogue ----
    #pragma unroll
    for (int mt = 0; mt < 4; mt++) {
        #pragma unroll
        for (int nt = 0; nt < 4; nt++) {
            int r0 = bm + warp_m * 64 + mt * 16 + g;
            int cc = bn + warp_n * 32 + nt * 8 + tg * 2;
            #pragma unroll
            for (int half = 0; half < 2; half++) {
                int r = r0 + half * 8;
                float v0 = acc[mt][nt][half * 2 + 0];
                float v1 = acc[mt][nt][half * 2 + 1];
                size_t gix = (size_t)r * ldc + cc;
                float o0, o1;
                if (EPI == EPI_GATE) {
                    float gt0 = 1.f / (1.f + expf(-(v0 + bias[cc])));
                    float gt1 = 1.f / (1.f + expf(-(v1 + bias[cc + 1])));
                    o0 = gt0 * res0[gix]     + (1.f - gt0) * res1[gix];
                    o1 = gt1 * res0[gix + 1] + (1.f - gt1) * res1[gix + 1];
                } else if (EPI == EPI_SCALE) {
                    o0 = v0 * scale; o1 = v1 * scale;
                } else if (EPI == EPI_ADD) {
                    o0 = v0 + res0[gix]; o1 = v1 + res0[gix + 1];
                } else if (EPI == EPI_GELU) {
                    float x0 = v0 + bias[cc], x1 = v1 + bias[cc + 1];
                    o0 = 0.5f * x0 * (1.f + erff(x0 * 0.70710678118654752440f));
                    o1 = 0.5f * x1 * (1.f + erff(x1 * 0.70710678118654752440f));
                } else { // EPI_BIAS_RES
                    o0 = v0 + bias[cc]     + res0[gix];
                    o1 = v1 + bias[cc + 1] + res0[gix + 1];
                }
                if (EPI == EPI_GATE || EPI == EPI_ADD || EPI == EPI_BIAS_RES)
                    *reinterpret_cast<float2*>(&C[gix]) = make_float2(o0, o1);
                if (EPI == EPI_GATE || EPI == EPI_SCALE || EPI == EPI_GELU)
                    *reinterpret_cast<__half2*>(&Ch[gix]) = __floats2half2_rn(o0, o1);
            }
        }
    }
}

// ---------------------------------------------------------------------------
// fp32 -> fp16 convert of TWO arrays in one pass
// ---------------------------------------------------------------------------
__global__ void __launch_bounds__(256)
convert2_h(const float* __restrict__ a, __half* __restrict__ oa,
           const float* __restrict__ b, __half* __restrict__ ob)
{
    size_t i4 = (size_t)blockIdx.x * 256 + threadIdx.x;
    float4 va = reinterpret_cast<const float4*>(a)[i4];
    float4 vb = reinterpret_cast<const float4*>(b)[i4];
    reinterpret_cast<__half2*>(oa)[i4 * 2]     = __floats2half2_rn(va.x, va.y);
    reinterpret_cast<__half2*>(oa)[i4 * 2 + 1] = __floats2half2_rn(va.z, va.w);
    reinterpret_cast<__half2*>(ob)[i4 * 2]     = __floats2half2_rn(vb.x, vb.y);
    reinterpret_cast<__half2*>(ob)[i4 * 2 + 1] = __floats2half2_rn(vb.z, vb.w);
}

// ---------------------------------------------------------------------------
// Tiled transpose + convert; optionally also writes the straight fp16 copy.
// grid (C/32, R/32, batch), block (32,8)
// ---------------------------------------------------------------------------
__global__ void __launch_bounds__(256)
transpose_h(const float* __restrict__ in, __half* __restrict__ out_t,
            __half* __restrict__ out_c, int R, int C)
{
    __shared__ float t[32][33];
    in    += (size_t)blockIdx.z * R * C;
    out_t += (size_t)blockIdx.z * R * C;
    if (out_c) out_c += (size_t)blockIdx.z * R * C;
    int r0 = blockIdx.y * 32, c0 = blockIdx.x * 32;
    int x = threadIdx.x, y = threadIdx.y;
    #pragma unroll
    for (int i = 0; i < 32; i += 8) {
        float v = in[(size_t)(r0 + y + i) * C + c0 + x];
        t[y + i][x] = v;
        if (out_c) out_c[(size_t)(r0 + y + i) * C + c0 + x] = __float2half_rn(v);
    }
    __syncthreads();
    #pragma unroll
    for (int i = 0; i < 32; i += 8)
        out_t[(size_t)(c0 + y + i) * R + r0 + x] = __float2half_rn(t[x][y + i]);
}

// ---------------------------------------------------------------------------
// Warp helpers
// ---------------------------------------------------------------------------
__device__ __forceinline__ float warpMax(float v) {
    #pragma unroll
    for (int o = 16; o > 0; o >>= 1) v = fmaxf(v, __shfl_xor_sync(0xffffffffu, v, o));
    return v;
}
__device__ __forceinline__ float warpSum(float v) {
    #pragma unroll
    for (int o = 16; o > 0; o >>= 1) v += __shfl_xor_sync(0xffffffffu, v, o);
    return v;
}

// ---------------------------------------------------------------------------
// Row softmax over 2048 fp16 logits, in place (fp32 math inside)
// ---------------------------------------------------------------------------
__global__ void __launch_bounds__(256)
softmax_kernel(__half* __restrict__ S)
{
    __half* p = S + (size_t)blockIdx.x * SEQ;
    const int tid  = threadIdx.x;
    const int lane = tid & 31;
    const int wid  = tid >> 5;
    __shared__ float sh[8];

    __half2 hv[4];
    *reinterpret_cast<float4*>(hv) = *reinterpret_cast<const float4*>(&p[tid * 8]);
    float v[8];
    #pragma unroll
    for (int i = 0; i < 4; i++) {
        float2 f = __half22float2(hv[i]);
        v[i*2] = f.x; v[i*2+1] = f.y;
    }

    float m = v[0];
    #pragma unroll
    for (int i = 1; i < 8; i++) m = fmaxf(m, v[i]);
    m = warpMax(m);
    if (lane == 0) sh[wid] = m;
    __syncthreads();
    m = sh[0];
    #pragma unroll
    for (int w = 1; w < 8; w++) m = fmaxf(m, sh[w]);
    __syncthreads();

    float s = 0.f;
    #pragma unroll
    for (int i = 0; i < 8; i++) { v[i] = expf(v[i] - m); s += v[i]; }
    s = warpSum(s);
    if (lane == 0) sh[wid] = s;
    __syncthreads();
    float tot = sh[0];
    #pragma unroll
    for (int w = 1; w < 8; w++) tot += sh[w];
    float inv = 1.f / tot;

    #pragma unroll
    for (int i = 0; i < 4; i++)
        hv[i] = __floats2half2_rn(v[i*2] * inv, v[i*2+1] * inv);
    *reinterpret_cast<float4*>(&p[tid * 8]) = *reinterpret_cast<float4*>(hv);
}

// ---------------------------------------------------------------------------
// LayerNorm over last dim (512); optional fp16 companion output
// ---------------------------------------------------------------------------
__global__ void __launch_bounds__(128)
layernorm_kernel(const float* __restrict__ in, float* __restrict__ out,
                 __half* __restrict__ out_h,
                 const float* __restrict__ gamma, const float* __restrict__ beta)
{
    const size_t base = (size_t)blockIdx.x * DIM;
    const int tid  = threadIdx.x;
    const int lane = tid & 31;
    const int wid  = tid >> 5;
    __shared__ float shs[4], shq[4];

    float4 x = *reinterpret_cast<const float4*>(&in[base + tid * 4]);
    float s  = x.x + x.y + x.z + x.w;
    float ss = x.x * x.x + x.y * x.y + x.z * x.z + x.w * x.w;
    s  = warpSum(s);
    ss = warpSum(ss);
    if (lane == 0) { shs[wid] = s; shq[wid] = ss; }
    __syncthreads();
    float sum = shs[0] + shs[1] + shs[2] + shs[3];
    float sq  = shq[0] + shq[1] + shq[2] + shq[3];
    float mu  = sum * (1.f / DIM);
    float var = sq * (1.f / DIM) - mu * mu;
    float rs  = rsqrtf(var + 1e-5f);

    float4 gm = *reinterpret_cast<const float4*>(&gamma[tid * 4]);
    float4 bt = *reinterpret_cast<const float4*>(&beta[tid * 4]);
    float4 o;
    o.x = (x.x - mu) * rs * gm.x + bt.x;
    o.y = (x.y - mu) * rs * gm.y + bt.y;
    o.z = (x.z - mu) * rs * gm.z + bt.z;
    o.w = (x.w - mu) * rs * gm.w + bt.w;
    *reinterpret_cast<float4*>(&out[base + tid * 4]) = o;
    if (out_h) {
        *reinterpret_cast<__half2*>(&out_h[base + tid * 4])     = __floats2half2_rn(o.x, o.y);
        *reinterpret_cast<__half2*>(&out_h[base + tid * 4 + 2]) = __floats2half2_rn(o.z, o.w);
    }
}

// ---------------------------------------------------------------------------
// Launch
// ---------------------------------------------------------------------------
extern "C" void kernel_launch(void* const* d_in, const int* in_sizes, int n_in,
                              void* d_out, int out_size)
{
    const float* Noise = (const float*)d_in[0];
    const float* X     = (const float*)d_in[1];
    const float* cond  = (const float*)d_in[2];
    const float* Wg    = (const float*)d_in[3];
    const float* bg    = (const float*)d_in[4];
    const float* W1    = (const float*)d_in[5];
    const float* b1    = (const float*)d_in[6];
    const float* W2    = (const float*)d_in[7];
    const float* b2    = (const float*)d_in[8];
    const float* g1    = (const float*)d_in[9];
    const float* be1   = (const float*)d_in[10];
    const float* g2    = (const float*)d_in[11];
    const float* be2   = (const float*)d_in[12];
    float* out = (float*)d_out;

    float *fused, *q, *y;
    __half *fusedh, *attnh, *qh, *hh, *noiseh, *condh, *xh, *xth, *wgth, *w1th, *w2th;
    cudaGetSymbolAddress((void**)&fused,  g_fused);
    cudaGetSymbolAddress((void**)&q,      g_q);
    cudaGetSymbolAddress((void**)&y,      g_y);
    cudaGetSymbolAddress((void**)&fusedh, g_fusedh);
    cudaGetSymbolAddress((void**)&attnh,  g_attnh);
    cudaGetSymbolAddress((void**)&qh,     g_qh);
    cudaGetSymbolAddress((void**)&hh,     g_hh);
    cudaGetSymbolAddress((void**)&noiseh, g_noiseh);
    cudaGetSymbolAddress((void**)&condh,  g_condh);
    cudaGetSymbolAddress((void**)&xh,     g_xh);
    cudaGetSymbolAddress((void**)&xth,    g_xth);
    cudaGetSymbolAddress((void**)&wgth,   g_wgth);
    cudaGetSymbolAddress((void**)&w1th,   g_w1th);
    cudaGetSymbolAddress((void**)&w2th,   g_w2th);

    cudaFuncSetAttribute(gemm_mma<EPI_GATE, true>,      cudaFuncAttributeMaxDynamicSharedMemorySize, SMEM_BYTES_G);
    cudaFuncSetAttribute(gemm_mma<EPI_SCALE, false>,    cudaFuncAttributeMaxDynamicSharedMemorySize, SMEM_BYTES_G);
    cudaFuncSetAttribute(gemm_mma<EPI_ADD, false>,      cudaFuncAttributeMaxDynamicSharedMemorySize, SMEM_BYTES_G);
    cudaFuncSetAttribute(gemm_mma<EPI_GELU, false>,     cudaFuncAttributeMaxDynamicSharedMemorySize, SMEM_BYTES_G);
    cudaFuncSetAttribute(gemm_mma<EPI_BIAS_RES, false>, cudaFuncAttributeMaxDynamicSharedMemorySize, SMEM_BYTES_G);

    const float scale = 0.04419417382415922f;  // 1/sqrt(512)
    const int NEL = NTOK * DIM;

    // 0. fp16 conversions + transposes (fused)
    convert2_h<<<NEL / 4 / 256, 256>>>(Noise, noiseh, cond, condh);
    transpose_h<<<dim3(DIM / 32, 2 * DIM / 32, 1), dim3(32, 8)>>>(Wg, wgth, nullptr, 2 * DIM, DIM);
    transpose_h<<<dim3(2 * DIM / 32, DIM / 32, 1), dim3(32, 8)>>>(W1, w1th, nullptr, DIM, 2 * DIM);
    transpose_h<<<dim3(DIM / 32, 2 * DIM / 32, 1), dim3(32, 8)>>>(W2, w2th, nullptr, 2 * DIM, DIM);
    transpose_h<<<dim3(DIM / 32, SEQ / 32, BATCH), dim3(32, 8)>>>(X, xth, xh, SEQ, DIM);

    // 1. gate+fuse: sigmoid(concat(Noise,cond) @ Wg + bg) blend
    gemm_mma<EPI_GATE, true><<<dim3(DIM / BN, NTOK / BM, 1), NTHREADS, SMEM_BYTES_G>>>(
        noiseh, condh, wgth, fused, fusedh,
        2 * DIM, 2 * DIM, 2 * DIM, DIM,
        0, 0, 0, bg, Noise, cond, 0.f);

    // 2. logits = fused @ X^T * scale -> fp16 attnh
    gemm_mma<EPI_SCALE, false><<<dim3(SEQ / BN, SEQ / BM, BATCH), NTHREADS, SMEM_BYTES_G>>>(
        fusedh, nullptr, xh, nullptr, attnh,
        DIM, DIM, DIM, SEQ,
        (size_t)SEQ * DIM, (size_t)SEQ * DIM, (size_t)SEQ * SEQ,
        nullptr, nullptr, nullptr, scale);

    // 3. softmax in place (fp16)
    softmax_kernel<<<NTOK, 256>>>(attnh);

    // 4. fused += attn @ X
    gemm_mma<EPI_ADD, false><<<dim3(DIM / BN, SEQ / BM, BATCH), NTHREADS, SMEM_BYTES_G>>>(
        attnh, nullptr, xth, fused, nullptr,
        SEQ, SEQ, SEQ, DIM,
        (size_t)SEQ * SEQ, (size_t)DIM * SEQ, (size_t)SEQ * DIM,
        nullptr, fused, nullptr, 0.f);

    // 5. q = LN1(fused) (+ fp16)
    layernorm_kernel<<<NTOK, 128>>>(fused, q, qh, g1, be1);

    // 6. h = gelu(q @ W1 + b1) -> fp16
    gemm_mma<EPI_GELU, false><<<dim3(2 * DIM / BN, NTOK / BM, 1), NTHREADS, SMEM_BYTES_G>>>(
        qh, nullptr, w1th, nullptr, hh,
        DIM, DIM, DIM, 2 * DIM,
        0, 0, 0, b1, nullptr, nullptr, 0.f);

    // 7. y = h @ W2 + b2 + q
    gemm_mma<EPI_BIAS_RES, false><<<dim3(DIM / BN, NTOK / BM, 1), NTHREADS, SMEM_BYTES_G>>>(
        hh, nullptr, w2th, y, nullptr,
        2 * DIM, 2 * DIM, 2 * DIM, DIM,
        0, 0, 0, b2, q, nullptr, 0.f);

    // 8. out = LN2(y)
    layernorm_kernel<<<NTOK, 128>>>(y, out, nullptr, g2, be2);
}

// round 14
// speedup vs baseline: 1.1185x; 1.1185x over previous
#include <cuda_runtime.h>
#include <cuda_fp16.h>
#include <math.h>
#include <stdint.h>

// ---------------------------------------------------------------------------
// Problem constants
// ---------------------------------------------------------------------------
#define BATCH   8
#define SEQ     2048
#define DIM     512
#define NTOK    (BATCH * SEQ)          // 16384

// GEMM tiling (mma.sync m16n8k16 fp16) — R10 proven shape
#define BM 128
#define BN 128
#define BK 64
#define NTHREADS 256                   // 8 warps, 2x4, 64x32 warp tiles
#define STAGES 3

// smem pitch in fp16: 64 k + 8 pad = 72 (144B rows; ldmatrix conflict-free)
#define PA 72
#define SBUFA (128 * PA)
#define SBUFB (128 * PA)
#define STAGE_H (SBUFA + SBUFB)
#define SMEM_BYTES_G (STAGES * STAGE_H * 2)   // 110,592 B -> 2 CTAs/SM

// Epilogue tags
#define EPI_GATE     0
#define EPI_SCALE    1
#define EPI_ADD      2
#define EPI_GELU     3
#define EPI_BIAS_RES 4

// ---------------------------------------------------------------------------
// Scratch (device globals: allocation-free rule)
// ---------------------------------------------------------------------------
__device__ float  g_fused  [(size_t)NTOK * DIM];         // PV output (fp32)
__device__ float  g_y      [(size_t)NTOK * DIM];         // FFN2 output (fp32)
__device__ __half g_fusedh [(size_t)NTOK * DIM];
__device__ __half g_attnh  [(size_t)BATCH * SEQ * SEQ];  // logits then weights
__device__ __half g_qh     [(size_t)NTOK * DIM];
__device__ __half g_hh     [(size_t)NTOK * 2 * DIM];
__device__ __half g_noiseh [(size_t)NTOK * DIM];
__device__ __half g_condh  [(size_t)NTOK * DIM];
__device__ __half g_xh     [(size_t)NTOK * DIM];         // X fp16 [S,D]
__device__ __half g_xth    [(size_t)BATCH * DIM * SEQ];  // X^T fp16 [D,S]
__device__ __half g_wgth   [(size_t)DIM * 2 * DIM];
__device__ __half g_w1th   [(size_t)2 * DIM * DIM];
__device__ __half g_w2th   [(size_t)DIM * 2 * DIM];

// ---------------------------------------------------------------------------
// PTX helpers
// ---------------------------------------------------------------------------
__device__ __forceinline__ uint32_t smem_u32(const void* p) {
    uint32_t a;
    asm("{ .reg .u64 t; cvta.to.shared.u64 t, %1; cvt.u32.u64 %0, t; }" : "=r"(a) : "l"(p));
    return a;
}
__device__ __forceinline__ void cp16(uint32_t saddr, const void* gaddr) {
    asm volatile("cp.async.cg.shared.global [%0], [%1], 16;" :: "r"(saddr), "l"(gaddr));
}
__device__ __forceinline__ void cp_commit() {
    asm volatile("cp.async.commit_group;" ::: "memory");
}
template<int N>
__device__ __forceinline__ void cp_wait() {
    asm volatile("cp.async.wait_group %0;" :: "n"(N) : "memory");
}
__device__ __forceinline__ void mma_f16(float* c, uint32_t a0, uint32_t a1,
                                        uint32_t a2, uint32_t a3,
                                        uint32_t b0, uint32_t b1) {
    asm volatile("mma.sync.aligned.m16n8k16.row.col.f32.f16.f16.f32 "
                 "{%0,%1,%2,%3}, {%4,%5,%6,%7}, {%8,%9}, {%0,%1,%2,%3};"
                 : "+f"(c[0]), "+f"(c[1]), "+f"(c[2]), "+f"(c[3])
                 : "r"(a0), "r"(a1), "r"(a2), "r"(a3), "r"(b0), "r"(b1));
}
__device__ __forceinline__ void ldsm4(uint32_t& r0, uint32_t& r1, uint32_t& r2,
                                      uint32_t& r3, uint32_t addr) {
    asm volatile("ldmatrix.sync.aligned.m8n8.x4.shared.b16 {%0,%1,%2,%3}, [%4];"
                 : "=r"(r0), "=r"(r1), "=r"(r2), "=r"(r3) : "r"(addr));
}

// ---------------------------------------------------------------------------
// fp16 tensor-core GEMM: C[M,N] = A[M,K] * B^T, A [M,K], B [N,K] (K-contig).
// 128x128x64 CTA tile, 8 warps (2x4), 64x32 warp tiles, ldmatrix fragments,
// 3-stage cp.async ring, 1 barrier per K=64 iter.  fp32 accumulate.
// SPLITA: A cols [0,512) from A, [512,1024) from A2 (virtual concat).
// Residual side-inputs are fp16 (hres0/hres1).
// Output: GATE/SCALE/GELU -> Ch (fp16);  ADD/BIAS_RES -> C (fp32).
// ---------------------------------------------------------------------------
template<int EPI, bool SPLITA>
__global__ void __launch_bounds__(NTHREADS, 2)
gemm_mma(const __half* __restrict__ A, const __half* __restrict__ A2,
         const __half* __restrict__ B,
         float* __restrict__ C, __half* __restrict__ Ch,
         int K, int lda, int ldb, int ldc,
         size_t strA, size_t strB, size_t strC,
         const float* __restrict__ bias,
         const __half* __restrict__ hres0,
         const __half* __restrict__ hres1,
         float scale)
{
    extern __shared__ __half hsm[];

    const int z = blockIdx.z;
    A += (size_t)z * strA;
    B += (size_t)z * strB;
    if (C)  C  += (size_t)z * strC;
    if (Ch) Ch += (size_t)z * strC;
    if (hres0) hres0 += (size_t)z * strC;
    if (hres1) hres1 += (size_t)z * strC;

    const int bm   = blockIdx.y * BM;
    const int bn   = blockIdx.x * BN;
    const int tid  = threadIdx.x;
    const int wid  = tid >> 5;
    const int lane = tid & 31;
    const int warp_m = wid & 1;        // 0..1 -> 64 rows
    const int warp_n = wid >> 1;       // 0..3 -> 32 cols
    const int g  = lane >> 2;          // 0..7
    const int tg = lane & 3;           // 0..3
    const int quad  = lane >> 3;       // 0..3
    const int rowin = lane & 7;        // 0..7

    const int a_row = (quad & 1) * 8 + rowin;
    const int a_col = (quad >> 1) * 8;
    const int b_row = (quad >> 1) * 8 + rowin;
    const int b_col = (quad & 1) * 8;

    const uint32_t smB = smem_u32(hsm);

    float acc[4][4][4];
    #pragma unroll
    for (int i = 0; i < 4; i++)
        #pragma unroll
        for (int j = 0; j < 4; j++)
            #pragma unroll
            for (int e = 0; e < 4; e++) acc[i][j][e] = 0.f;

    const int nit = K / BK;

    auto prefetch = [&](int it) {
        const int kk = it * BK;
        const int st = it % STAGES;
        const uint32_t sa = smB + (uint32_t)(st * STAGE_H) * 2u;
        const uint32_t sb = sa + (uint32_t)SBUFA * 2u;
        #pragma unroll
        for (int t = 0; t < 4; t++) {
            int id = tid + t * NTHREADS;       // 0..1023
            int r  = id >> 3;                  // 0..127
            int c8 = id & 7;
            int col = kk + c8 * 8;
            const __half* src;
            if (SPLITA) {
                src = (col < DIM) ? (A  + (size_t)(bm + r) * DIM + col)
                                  : (A2 + (size_t)(bm + r) * DIM + (col - DIM));
            } else {
                src = A + (size_t)(bm + r) * lda + col;
            }
            cp16(sa + (uint32_t)(r * PA + c8 * 8) * 2u, src);
        }
        #pragma unroll
        for (int t = 0; t < 4; t++) {
            int id = tid + t * NTHREADS;
            int r  = id >> 3;
            int c8 = id & 7;
            cp16(sb + (uint32_t)(r * PA + c8 * 8) * 2u,
                 B + (size_t)(bn + r) * ldb + kk + c8 * 8);
        }
        cp_commit();
    };

    prefetch(0);
    prefetch(1);

    #pragma unroll 1
    for (int it = 0; it < nit; it++) {
        cp_wait<1>();
        __syncthreads();
        if (it + 2 < nit) prefetch(it + 2);

        const int st = it % STAGES;
        const uint32_t sa = smB + (uint32_t)(st * STAGE_H) * 2u;
        const uint32_t sb = sa + (uint32_t)SBUFA * 2u;

        #pragma unroll
        for (int ks = 0; ks < 4; ks++) {
            const int kc = ks * 16;
            uint32_t af[4][4];
            #pragma unroll
            for (int mt = 0; mt < 4; mt++) {
                int m = warp_m * 64 + mt * 16;
                uint32_t addr = sa + (uint32_t)((m + a_row) * PA + kc + a_col) * 2u;
                ldsm4(af[mt][0], af[mt][1], af[mt][2], af[mt][3], addr);
            }
            uint32_t bf[4][2];
            #pragma unroll
            for (int np = 0; np < 2; np++) {
                int n = warp_n * 32 + np * 16;
                uint32_t addr = sb + (uint32_t)((n + b_row) * PA + kc + b_col) * 2u;
                ldsm4(bf[np*2][0], bf[np*2][1], bf[np*2+1][0], bf[np*2+1][1], addr);
            }
            #pragma unroll
            for (int mt = 0; mt < 4; mt++)
                #pragma unroll
                for (int nt = 0; nt < 4; nt++)
                    mma_f16(acc[mt][nt], af[mt][0], af[mt][1], af[mt][2], af[mt][3],
                            bf[nt][0], bf[nt][1]);
        }
    }

    // ---- epilogue ----
    #pragma unroll
    for (int mt = 0; mt < 4; mt++) {
        #pragma unroll
        for (int nt = 0; nt < 4; nt++) {
            int r0 = bm + warp_m * 64 + mt * 16 + g;
            int cc = bn + warp_n * 32 + nt * 8 + tg * 2;
            #pragma unroll
            for (int half = 0; half < 2; half++) {
                int r = r0 + half * 8;
                float v0 = acc[mt][nt][half * 2 + 0];
                float v1 = acc[mt][nt][half * 2 + 1];
                size_t gix = (size_t)r * ldc + cc;
                float o0, o1;
                if (EPI == EPI_GATE) {
                    float2 n2 = __half22float2(*reinterpret_cast<const __half2*>(&hres0[gix]));
                    float2 c2 = __half22float2(*reinterpret_cast<const __half2*>(&hres1[gix]));
                    float gt0 = 1.f / (1.f + expf(-(v0 + bias[cc])));
                    float gt1 = 1.f / (1.f + expf(-(v1 + bias[cc + 1])));
                    o0 = gt0 * n2.x + (1.f - gt0) * c2.x;
                    o1 = gt1 * n2.y + (1.f - gt1) * c2.y;
                } else if (EPI == EPI_SCALE) {
                    o0 = v0 * scale; o1 = v1 * scale;
                } else if (EPI == EPI_ADD) {
                    float2 r2 = __half22float2(*reinterpret_cast<const __half2*>(&hres0[gix]));
                    o0 = v0 + r2.x; o1 = v1 + r2.y;
                } else if (EPI == EPI_GELU) {
                    float x0 = v0 + bias[cc], x1 = v1 + bias[cc + 1];
                    o0 = 0.5f * x0 * (1.f + erff(x0 * 0.70710678118654752440f));
                    o1 = 0.5f * x1 * (1.f + erff(x1 * 0.70710678118654752440f));
                } else { // EPI_BIAS_RES
                    float2 r2 = __half22float2(*reinterpret_cast<const __half2*>(&hres0[gix]));
                    o0 = v0 + bias[cc]     + r2.x;
                    o1 = v1 + bias[cc + 1] + r2.y;
                }
                if (EPI == EPI_ADD || EPI == EPI_BIAS_RES)
                    *reinterpret_cast<float2*>(&C[gix]) = make_float2(o0, o1);
                else
                    *reinterpret_cast<__half2*>(&Ch[gix]) = __floats2half2_rn(o0, o1);
            }
        }
    }
}

// ---------------------------------------------------------------------------
// fp32 -> fp16 convert of TWO arrays in one pass
// ---------------------------------------------------------------------------
__global__ void __launch_bounds__(256)
convert2_h(const float* __restrict__ a, __half* __restrict__ oa,
           const float* __restrict__ b, __half* __restrict__ ob)
{
    size_t i4 = (size_t)blockIdx.x * 256 + threadIdx.x;
    float4 va = reinterpret_cast<const float4*>(a)[i4];
    float4 vb = reinterpret_cast<const float4*>(b)[i4];
    reinterpret_cast<__half2*>(oa)[i4 * 2]     = __floats2half2_rn(va.x, va.y);
    reinterpret_cast<__half2*>(oa)[i4 * 2 + 1] = __floats2half2_rn(va.z, va.w);
    reinterpret_cast<__half2*>(ob)[i4 * 2]     = __floats2half2_rn(vb.x, vb.y);
    reinterpret_cast<__half2*>(ob)[i4 * 2 + 1] = __floats2half2_rn(vb.z, vb.w);
}

// ---------------------------------------------------------------------------
// Tiled transpose + convert; optionally also writes the straight fp16 copy.
// ---------------------------------------------------------------------------
__global__ void __launch_bounds__(256)
transpose_h(const float* __restrict__ in, __half* __restrict__ out_t,
            __half* __restrict__ out_c, int R, int C)
{
    __shared__ float t[32][33];
    in    += (size_t)blockIdx.z * R * C;
    out_t += (size_t)blockIdx.z * R * C;
    if (out_c) out_c += (size_t)blockIdx.z * R * C;
    int r0 = blockIdx.y * 32, c0 = blockIdx.x * 32;
    int x = threadIdx.x, y = threadIdx.y;
    #pragma unroll
    for (int i = 0; i < 32; i += 8) {
        float v = in[(size_t)(r0 + y + i) * C + c0 + x];
        t[y + i][x] = v;
        if (out_c) out_c[(size_t)(r0 + y + i) * C + c0 + x] = __float2half_rn(v);
    }
    __syncthreads();
    #pragma unroll
    for (int i = 0; i < 32; i += 8)
        out_t[(size_t)(c0 + y + i) * R + r0 + x] = __float2half_rn(t[x][y + i]);
}

// ---------------------------------------------------------------------------
// Warp helpers
// ---------------------------------------------------------------------------
__device__ __forceinline__ float warpMax(float v) {
    #pragma unroll
    for (int o = 16; o > 0; o >>= 1) v = fmaxf(v, __shfl_xor_sync(0xffffffffu, v, o));
    return v;
}
__device__ __forceinline__ float warpSum(float v) {
    #pragma unroll
    for (int o = 16; o > 0; o >>= 1) v += __shfl_xor_sync(0xffffffffu, v, o);
    return v;
}

// ---------------------------------------------------------------------------
// Row softmax over 2048 fp16 logits, in place (fp32 math inside)
// ---------------------------------------------------------------------------
__global__ void __launch_bounds__(256)
softmax_kernel(__half* __restrict__ S)
{
    __half* p = S + (size_t)blockIdx.x * SEQ;
    const int tid  = threadIdx.x;
    const int lane = tid & 31;
    const int wid  = tid >> 5;
    __shared__ float sh[8];

    __half2 hv[4];
    *reinterpret_cast<float4*>(hv) = *reinterpret_cast<const float4*>(&p[tid * 8]);
    float v[8];
    #pragma unroll
    for (int i = 0; i < 4; i++) {
        float2 f = __half22float2(hv[i]);
        v[i*2] = f.x; v[i*2+1] = f.y;
    }

    float m = v[0];
    #pragma unroll
    for (int i = 1; i < 8; i++) m = fmaxf(m, v[i]);
    m = warpMax(m);
    if (lane == 0) sh[wid] = m;
    __syncthreads();
    m = sh[0];
    #pragma unroll
    for (int w = 1; w < 8; w++) m = fmaxf(m, sh[w]);
    __syncthreads();

    float s = 0.f;
    #pragma unroll
    for (int i = 0; i < 8; i++) { v[i] = expf(v[i] - m); s += v[i]; }
    s = warpSum(s);
    if (lane == 0) sh[wid] = s;
    __syncthreads();
    float tot = sh[0];
    #pragma unroll
    for (int w = 1; w < 8; w++) tot += sh[w];
    float inv = 1.f / tot;

    #pragma unroll
    for (int i = 0; i < 4; i++)
        hv[i] = __floats2half2_rn(v[i*2] * inv, v[i*2+1] * inv);
    *reinterpret_cast<float4*>(&p[tid * 8]) = *reinterpret_cast<float4*>(hv);
}

// ---------------------------------------------------------------------------
// LayerNorm over last dim (512); fp32 and/or fp16 outputs (either may be null)
// ---------------------------------------------------------------------------
__global__ void __launch_bounds__(128)
layernorm_kernel(const float* __restrict__ in, float* __restrict__ out,
                 __half* __restrict__ out_h,
                 const float* __restrict__ gamma, const float* __restrict__ beta)
{
    const size_t base = (size_t)blockIdx.x * DIM;
    const int tid  = threadIdx.x;
    const int lane = tid & 31;
    const int wid  = tid >> 5;
    __shared__ float shs[4], shq[4];

    float4 x = *reinterpret_cast<const float4*>(&in[base + tid * 4]);
    float s  = x.x + x.y + x.z + x.w;
    float ss = x.x * x.x + x.y * x.y + x.z * x.z + x.w * x.w;
    s  = warpSum(s);
    ss = warpSum(ss);
    if (lane == 0) { shs[wid] = s; shq[wid] = ss; }
    __syncthreads();
    float sum = shs[0] + shs[1] + shs[2] + shs[3];
    float sq  = shq[0] + shq[1] + shq[2] + shq[3];
    float mu  = sum * (1.f / DIM);
    float var = sq * (1.f / DIM) - mu * mu;
    float rs  = rsqrtf(var + 1e-5f);

    float4 gm = *reinterpret_cast<const float4*>(&gamma[tid * 4]);
    float4 bt = *reinterpret_cast<const float4*>(&beta[tid * 4]);
    float4 o;
    o.x = (x.x - mu) * rs * gm.x + bt.x;
    o.y = (x.y - mu) * rs * gm.y + bt.y;
    o.z = (x.z - mu) * rs * gm.z + bt.z;
    o.w = (x.w - mu) * rs * gm.w + bt.w;
    if (out)
        *reinterpret_cast<float4*>(&out[base + tid * 4]) = o;
    if (out_h) {
        *reinterpret_cast<__half2*>(&out_h[base + tid * 4])     = __floats2half2_rn(o.x, o.y);
        *reinterpret_cast<__half2*>(&out_h[base + tid * 4 + 2]) = __floats2half2_rn(o.z, o.w);
    }
}

// ---------------------------------------------------------------------------
// Launch
// ---------------------------------------------------------------------------
extern "C" void kernel_launch(void* const* d_in, const int* in_sizes, int n_in,
                              void* d_out, int out_size)
{
    const float* Noise = (const float*)d_in[0];
    const float* X     = (const float*)d_in[1];
    const float* cond  = (const float*)d_in[2];
    const float* Wg    = (const float*)d_in[3];
    const float* bg    = (const float*)d_in[4];
    const float* W1    = (const float*)d_in[5];
    const float* b1    = (const float*)d_in[6];
    const float* W2    = (const float*)d_in[7];
    const float* b2    = (const float*)d_in[8];
    const float* g1    = (const float*)d_in[9];
    const float* be1   = (const float*)d_in[10];
    const float* g2    = (const float*)d_in[11];
    const float* be2   = (const float*)d_in[12];
    float* out = (float*)d_out;

    float *fused, *y;
    __half *fusedh, *attnh, *qh, *hh, *noiseh, *condh, *xh, *xth, *wgth, *w1th, *w2th;
    cudaGetSymbolAddress((void**)&fused,  g_fused);
    cudaGetSymbolAddress((void**)&y,      g_y);
    cudaGetSymbolAddress((void**)&fusedh, g_fusedh);
    cudaGetSymbolAddress((void**)&attnh,  g_attnh);
    cudaGetSymbolAddress((void**)&qh,     g_qh);
    cudaGetSymbolAddress((void**)&hh,     g_hh);
    cudaGetSymbolAddress((void**)&noiseh, g_noiseh);
    cudaGetSymbolAddress((void**)&condh,  g_condh);
    cudaGetSymbolAddress((void**)&xh,     g_xh);
    cudaGetSymbolAddress((void**)&xth,    g_xth);
    cudaGetSymbolAddress((void**)&wgth,   g_wgth);
    cudaGetSymbolAddress((void**)&w1th,   g_w1th);
    cudaGetSymbolAddress((void**)&w2th,   g_w2th);

    cudaFuncSetAttribute(gemm_mma<EPI_GATE, true>,      cudaFuncAttributeMaxDynamicSharedMemorySize, SMEM_BYTES_G);
    cudaFuncSetAttribute(gemm_mma<EPI_SCALE, false>,    cudaFuncAttributeMaxDynamicSharedMemorySize, SMEM_BYTES_G);
    cudaFuncSetAttribute(gemm_mma<EPI_ADD, false>,      cudaFuncAttributeMaxDynamicSharedMemorySize, SMEM_BYTES_G);
    cudaFuncSetAttribute(gemm_mma<EPI_GELU, false>,     cudaFuncAttributeMaxDynamicSharedMemorySize, SMEM_BYTES_G);
    cudaFuncSetAttribute(gemm_mma<EPI_BIAS_RES, false>, cudaFuncAttributeMaxDynamicSharedMemorySize, SMEM_BYTES_G);

    const float scale = 0.04419417382415922f;  // 1/sqrt(512)
    const int NEL = NTOK * DIM;

    // 0. fp16 conversions + transposes
    convert2_h<<<NEL / 4 / 256, 256>>>(Noise, noiseh, cond, condh);
    transpose_h<<<dim3(DIM / 32, 2 * DIM / 32, 1), dim3(32, 8)>>>(Wg, wgth, nullptr, 2 * DIM, DIM);
    transpose_h<<<dim3(2 * DIM / 32, DIM / 32, 1), dim3(32, 8)>>>(W1, w1th, nullptr, DIM, 2 * DIM);
    transpose_h<<<dim3(DIM / 32, 2 * DIM / 32, 1), dim3(32, 8)>>>(W2, w2th, nullptr, 2 * DIM, DIM);
    transpose_h<<<dim3(DIM / 32, SEQ / 32, BATCH), dim3(32, 8)>>>(X, xth, xh, SEQ, DIM);

    // 1. gate+fuse -> fusedh (fp16 only; blend inputs fp16)
    gemm_mma<EPI_GATE, true><<<dim3(DIM / BN, NTOK / BM, 1), NTHREADS, SMEM_BYTES_G>>>(
        noiseh, condh, wgth, nullptr, fusedh,
        2 * DIM, 2 * DIM, 2 * DIM, DIM,
        0, 0, 0, bg, noiseh, condh, 0.f);

    // 2. logits = fused @ X^T * scale -> fp16 attnh
    gemm_mma<EPI_SCALE, false><<<dim3(SEQ / BN, SEQ / BM, BATCH), NTHREADS, SMEM_BYTES_G>>>(
        fusedh, nullptr, xh, nullptr, attnh,
        DIM, DIM, DIM, SEQ,
        (size_t)SEQ * DIM, (size_t)SEQ * DIM, (size_t)SEQ * SEQ,
        nullptr, nullptr, nullptr, scale);

    // 3. softmax in place (fp16)
    softmax_kernel<<<NTOK, 256>>>(attnh);

    // 4. fused(fp32) = attn @ X + fusedh (fp16 residual)
    gemm_mma<EPI_ADD, false><<<dim3(DIM / BN, SEQ / BM, BATCH), NTHREADS, SMEM_BYTES_G>>>(
        attnh, nullptr, xth, fused, nullptr,
        SEQ, SEQ, SEQ, DIM,
        (size_t)SEQ * SEQ, (size_t)DIM * SEQ, (size_t)SEQ * DIM,
        nullptr, fusedh, nullptr, 0.f);

    // 5. qh = LN1(fused)  (fp16 only)
    layernorm_kernel<<<NTOK, 128>>>(fused, nullptr, qh, g1, be1);

    // 6. h = gelu(q @ W1 + b1) -> fp16
    gemm_mma<EPI_GELU, false><<<dim3(2 * DIM / BN, NTOK / BM, 1), NTHREADS, SMEM_BYTES_G>>>(
        qh, nullptr, w1th, nullptr, hh,
        DIM, DIM, DIM, 2 * DIM,
        0, 0, 0, b1, nullptr, nullptr, 0.f);

    // 7. y(fp32) = h @ W2 + b2 + qh (fp16 residual)
    gemm_mma<EPI_BIAS_RES, false><<<dim3(DIM / BN, NTOK / BM, 1), NTHREADS, SMEM_BYTES_G>>>(
        hh, nullptr, w2th, y, nullptr,
        2 * DIM, 2 * DIM, 2 * DIM, DIM,
        0, 0, 0, b2, qh, nullptr, 0.f);

    // 8. out = LN2(y)
    layernorm_kernel<<<NTOK, 128>>>(y, out, nullptr, g2, be2);
}